// round 3
// baseline (speedup 1.0000x reference)
#include <cuda_runtime.h>
#include <math.h>
#include <float.h>

#define T_DIM 8192
#define D_DIM 512
#define N_SYN 4

// Scratch (device globals: no allocation allowed in kernel_launch)
__device__ float g_sq[T_DIM];
__device__ float g_dist[(size_t)T_DIM * T_DIM];   // 256 MB distance matrix
__device__ int   g_nb[T_DIM * 4];                 // 4 nearest neighbors (ranks 1..4)

// ---------------------------------------------------------------------------
// 1) Row squared norms: one warp per row
// ---------------------------------------------------------------------------
__global__ void sq_kernel(const float* __restrict__ X) {
    int warp = (blockIdx.x * blockDim.x + threadIdx.x) >> 5;
    int lane = threadIdx.x & 31;
    if (warp >= T_DIM) return;
    const float4* xr = reinterpret_cast<const float4*>(X + (size_t)warp * D_DIM);
    float s = 0.f;
#pragma unroll
    for (int c = 0; c < 4; c++) {
        float4 v = xr[lane + c * 32];
        s += v.x * v.x + v.y * v.y + v.z * v.z + v.w * v.w;
    }
#pragma unroll
    for (int o = 16; o > 0; o >>= 1) s += __shfl_down_sync(0xffffffffu, s, o);
    if (lane == 0) g_sq[warp] = s;
}

// ---------------------------------------------------------------------------
// 2) dist[i,j] = sqrt(max(sq_i + sq_j - 2 * <X_i, X_j>, 0))
//    128x128 tile per block, BK=8, 8x8 per thread, 256 threads.
// ---------------------------------------------------------------------------
__global__ __launch_bounds__(256) void dist_gemm_kernel(const float* __restrict__ X) {
    __shared__ float As[8][132];   // padded: conflict-free stores & 16B-aligned rows
    __shared__ float Bs[8][132];

    const int tid = threadIdx.x;
    const int rowTile = blockIdx.y * 128;
    const int colTile = blockIdx.x * 128;

    const int lr = tid >> 1;          // 0..127 load row
    const int lc = (tid & 1) * 4;     // 0 or 4  load col (float4)
    const int ty = tid >> 4;          // 0..15
    const int tx = tid & 15;          // 0..15

    float acc[8][8];
#pragma unroll
    for (int i = 0; i < 8; i++)
#pragma unroll
        for (int j = 0; j < 8; j++) acc[i][j] = 0.f;

    const float* Aptr = X + (size_t)(rowTile + lr) * D_DIM + lc;
    const float* Bptr = X + (size_t)(colTile + lr) * D_DIM + lc;

    for (int k0 = 0; k0 < D_DIM; k0 += 8) {
        float4 a = *reinterpret_cast<const float4*>(Aptr + k0);
        float4 b = *reinterpret_cast<const float4*>(Bptr + k0);
        __syncthreads();
        As[lc + 0][lr] = a.x; As[lc + 1][lr] = a.y;
        As[lc + 2][lr] = a.z; As[lc + 3][lr] = a.w;
        Bs[lc + 0][lr] = b.x; Bs[lc + 1][lr] = b.y;
        Bs[lc + 2][lr] = b.z; Bs[lc + 3][lr] = b.w;
        __syncthreads();
#pragma unroll
        for (int kk = 0; kk < 8; kk++) {
            float4 a0 = *reinterpret_cast<const float4*>(&As[kk][ty * 8]);
            float4 a1 = *reinterpret_cast<const float4*>(&As[kk][ty * 8 + 4]);
            float4 b0 = *reinterpret_cast<const float4*>(&Bs[kk][tx * 8]);
            float4 b1 = *reinterpret_cast<const float4*>(&Bs[kk][tx * 8 + 4]);
            float ra[8] = {a0.x, a0.y, a0.z, a0.w, a1.x, a1.y, a1.z, a1.w};
            float rb[8] = {b0.x, b0.y, b0.z, b0.w, b1.x, b1.y, b1.z, b1.w};
#pragma unroll
            for (int i = 0; i < 8; i++)
#pragma unroll
                for (int j = 0; j < 8; j++)
                    acc[i][j] = fmaf(ra[i], rb[j], acc[i][j]);
        }
    }

    // Epilogue: form distances and store (float4)
    float sqc[8];
#pragma unroll
    for (int j = 0; j < 8; j++) sqc[j] = g_sq[colTile + tx * 8 + j];

#pragma unroll
    for (int i = 0; i < 8; i++) {
        int r = rowTile + ty * 8 + i;
        float sqr = g_sq[r];
        float* orow = g_dist + (size_t)r * T_DIM + colTile + tx * 8;
        float4 o0, o1;
        o0.x = sqrtf(fmaxf(sqr + sqc[0] - 2.f * acc[i][0], 0.f));
        o0.y = sqrtf(fmaxf(sqr + sqc[1] - 2.f * acc[i][1], 0.f));
        o0.z = sqrtf(fmaxf(sqr + sqc[2] - 2.f * acc[i][2], 0.f));
        o0.w = sqrtf(fmaxf(sqr + sqc[3] - 2.f * acc[i][3], 0.f));
        o1.x = sqrtf(fmaxf(sqr + sqc[4] - 2.f * acc[i][4], 0.f));
        o1.y = sqrtf(fmaxf(sqr + sqc[5] - 2.f * acc[i][5], 0.f));
        o1.z = sqrtf(fmaxf(sqr + sqc[6] - 2.f * acc[i][6], 0.f));
        o1.w = sqrtf(fmaxf(sqr + sqc[7] - 2.f * acc[i][7], 0.f));
        *reinterpret_cast<float4*>(orow) = o0;
        *reinterpret_cast<float4*>(orow + 4) = o1;
    }
}

// ---------------------------------------------------------------------------
// 3) Per-row top-5 smallest (dist, idx) with jax.lax.top_k tie semantics:
//    smaller dist first; equal dist -> smaller index first.
// ---------------------------------------------------------------------------
__device__ __forceinline__ bool kless(float d1, int i1, float d2, int i2) {
    return (d1 < d2) || (d1 == d2 && i1 < i2);
}

__device__ __forceinline__ void insert5(float d, int j, float (&d5)[5], int (&i5)[5]) {
    if (kless(d, j, d5[4], i5[4])) {
        d5[4] = d; i5[4] = j;
#pragma unroll
        for (int p = 4; p > 0; p--) {
            if (kless(d5[p], i5[p], d5[p - 1], i5[p - 1])) {
                float td = d5[p]; d5[p] = d5[p - 1]; d5[p - 1] = td;
                int   ti = i5[p]; i5[p] = i5[p - 1]; i5[p - 1] = ti;
            }
        }
    }
}

__global__ __launch_bounds__(256) void topk_kernel() {
    __shared__ float sd[256][5];
    __shared__ int   si[256][5];
    __shared__ float wd[8][5];
    __shared__ int   wi[8][5];

    int row = blockIdx.x;
    const float* drow = g_dist + (size_t)row * T_DIM;

    float d5[5]; int i5[5];
#pragma unroll
    for (int r = 0; r < 5; r++) { d5[r] = FLT_MAX; i5[r] = 0x7fffffff; }

    for (int j = threadIdx.x; j < T_DIM; j += 256) {
        float d = drow[j];
        insert5(d, j, d5, i5);
    }
#pragma unroll
    for (int r = 0; r < 5; r++) { sd[threadIdx.x][r] = d5[r]; si[threadIdx.x][r] = i5[r]; }
    __syncthreads();

    int lane = threadIdx.x & 31, wid = threadIdx.x >> 5;
    if (lane == 0) {
#pragma unroll
        for (int r = 0; r < 5; r++) { d5[r] = sd[wid * 32][r]; i5[r] = si[wid * 32][r]; }
        for (int t = 1; t < 32; t++) {
#pragma unroll
            for (int r = 0; r < 5; r++)
                insert5(sd[wid * 32 + t][r], si[wid * 32 + t][r], d5, i5);
        }
#pragma unroll
        for (int r = 0; r < 5; r++) { wd[wid][r] = d5[r]; wi[wid][r] = i5[r]; }
    }
    __syncthreads();

    if (threadIdx.x == 0) {
#pragma unroll
        for (int r = 0; r < 5; r++) { d5[r] = wd[0][r]; i5[r] = wi[0][r]; }
        for (int t = 1; t < 8; t++) {
#pragma unroll
            for (int r = 0; r < 5; r++)
                insert5(wd[t][r], wi[t][r], d5, i5);
        }
        // rank 0 is self; keep ranks 1..4
#pragma unroll
        for (int r = 0; r < 4; r++) g_nb[row * 4 + r] = i5[r + 1];
    }
}

// ---------------------------------------------------------------------------
// 4) Interpolate: out[s] = X[i] + gaps[s] * (X[sel] - X[i]),  s = i*4 + n
// ---------------------------------------------------------------------------
__global__ __launch_bounds__(128) void synth_kernel(const float* __restrict__ X,
                                                    const float* __restrict__ gaps,
                                                    const int* __restrict__ choice,
                                                    float* __restrict__ out) {
    int s = blockIdx.x;
    int i = s >> 2;
    int c = choice[s];               // 0..3
    int sel = g_nb[i * 4 + c];
    float g = gaps[s];

    const float4* base = reinterpret_cast<const float4*>(X + (size_t)i * D_DIM);
    const float4* nb   = reinterpret_cast<const float4*>(X + (size_t)sel * D_DIM);
    float4* o = reinterpret_cast<float4*>(out + (size_t)s * D_DIM);

    int t = threadIdx.x;             // 128 threads * float4 = 512 floats
    float4 b = base[t], v = nb[t];
    float4 r;
    r.x = fmaf(g, v.x - b.x, b.x);
    r.y = fmaf(g, v.y - b.y, b.y);
    r.z = fmaf(g, v.z - b.z, b.z);
    r.w = fmaf(g, v.w - b.w, b.w);
    o[t] = r;
}

// ---------------------------------------------------------------------------
extern "C" void kernel_launch(void* const* d_in, const int* in_sizes, int n_in,
                              void* d_out, int out_size) {
    const float* X      = (const float*)d_in[0];   // [8192, 512]
    const float* gaps   = (const float*)d_in[1];   // [8192, 4]
    const int*   choice = (const int*)d_in[2];     // [8192, 4]
    float* out = (float*)d_out;                    // [32768, 512]

    sq_kernel<<<(T_DIM * 32 + 255) / 256, 256>>>(X);
    dist_gemm_kernel<<<dim3(T_DIM / 128, T_DIM / 128), 256>>>(X);
    topk_kernel<<<T_DIM, 256>>>();
    synth_kernel<<<T_DIM * N_SYN, 128>>>(X, gaps, choice, out);
}

// round 5
// speedup vs baseline: 1.2671x; 1.2671x over previous
#include <cuda_runtime.h>
#include <cuda_bf16.h>
#include <math.h>
#include <float.h>
#include <stdint.h>

#define T_DIM 8192
#define D_DIM 512
#define N_SYN 4
#define TS 128                    // CTA tile M=N
#define KC 32                     // k elems per smem stage
#define NSTAGE (D_DIM / KC)       // 16
#define LDK 36                    // padded smem row stride (floats): 16B-aligned, conflict-free
#define TILE_F (TS * LDK)         // floats per tile (4608)
#define STAGE_F (4 * TILE_F)      // AH AL BH BL (18432 floats)

// ---------------------------------------------------------------------------
// Device-global scratch
// ---------------------------------------------------------------------------
__device__ float g_sq[T_DIM];
__device__ float g_dist[(size_t)T_DIM * T_DIM];   // 256 MB
__device__ int   g_nb[T_DIM * 4];
__device__ float g_hi[(size_t)T_DIM * D_DIM];     // tf32-valued fp32, 16 MB
__device__ float g_lo[(size_t)T_DIM * D_DIM];     // tf32-valued fp32, 16 MB

// ---------------------------------------------------------------------------
// PTX helpers (all baseline sm_80+ -> legal on compute_103)
// ---------------------------------------------------------------------------
__device__ __forceinline__ uint32_t smem_u32(const void* p) {
    uint32_t a;
    asm("{ .reg .u64 t; cvta.to.shared.u64 t, %1; cvt.u32.u64 %0, t; }" : "=r"(a) : "l"(p));
    return a;
}
#define CP_ASYNC_CG(dst_u32, src_ptr) \
    asm volatile("cp.async.cg.shared.global [%0], [%1], 16;" :: "r"(dst_u32), "l"(src_ptr))
#define CP_COMMIT() asm volatile("cp.async.commit_group;" ::: "memory")
#define CP_WAIT(n)  asm volatile("cp.async.wait_group %0;" :: "n"(n) : "memory")

#define MMA_TF32(Cp, a, b) \
    asm volatile("mma.sync.aligned.m16n8k8.row.col.f32.tf32.tf32.f32 " \
        "{%0,%1,%2,%3}, {%4,%5,%6,%7}, {%8,%9}, {%0,%1,%2,%3};" \
        : "+f"((Cp)[0]), "+f"((Cp)[1]), "+f"((Cp)[2]), "+f"((Cp)[3]) \
        : "r"((a)[0]), "r"((a)[1]), "r"((a)[2]), "r"((a)[3]), \
          "r"((b)[0]), "r"((b)[1]))

// ---------------------------------------------------------------------------
// 1) Row squared norms (fp32): one warp per row
// ---------------------------------------------------------------------------
__global__ void sq_kernel(const float* __restrict__ X) {
    int warp = (blockIdx.x * blockDim.x + threadIdx.x) >> 5;
    int lane = threadIdx.x & 31;
    if (warp >= T_DIM) return;
    const float4* xr = reinterpret_cast<const float4*>(X + (size_t)warp * D_DIM);
    float s = 0.f;
#pragma unroll
    for (int c = 0; c < 4; c++) {
        float4 v = xr[lane + c * 32];
        s += v.x * v.x + v.y * v.y + v.z * v.z + v.w * v.w;
    }
#pragma unroll
    for (int o = 16; o > 0; o >>= 1) s += __shfl_down_sync(0xffffffffu, s, o);
    if (lane == 0) g_sq[warp] = s;
}

// ---------------------------------------------------------------------------
// 2) tf32 2-way split: x = hi + lo + r, |r| <= 2^-22 |x|
// ---------------------------------------------------------------------------
__global__ void split_kernel(const float* __restrict__ X) {
    int i = blockIdx.x * blockDim.x + threadIdx.x;   // over T*D/4
    float4 v = reinterpret_cast<const float4*>(X)[i];
    float xs[4] = {v.x, v.y, v.z, v.w};
    float h[4], l[4];
#pragma unroll
    for (int c = 0; c < 4; c++) {
        uint32_t hb, lb;
        asm("cvt.rna.tf32.f32 %0, %1;" : "=r"(hb) : "f"(xs[c]));
        float hf = __uint_as_float(hb);
        float r = xs[c] - hf;
        asm("cvt.rna.tf32.f32 %0, %1;" : "=r"(lb) : "f"(r));
        h[c] = hf;
        l[c] = __uint_as_float(lb);
    }
    reinterpret_cast<float4*>(g_hi)[i] = make_float4(h[0], h[1], h[2], h[3]);
    reinterpret_cast<float4*>(g_lo)[i] = make_float4(l[0], l[1], l[2], l[3]);
}

// ---------------------------------------------------------------------------
// 3) Triangular dist GEMM via mma.sync tf32 split (dot = hh + hl + lh)
//    256 threads = 8 warps (4x2), warp tile 32x64, CTA tile 128x128.
// ---------------------------------------------------------------------------
__global__ __launch_bounds__(256, 1) void dist_mma_kernel() {
    extern __shared__ __align__(16) float smf[];
    const int tid = threadIdx.x;
    const int lane = tid & 31, wid = tid >> 5;
    const int warpM = wid & 3;        // 0..3 -> m offset *32
    const int warpN = wid >> 2;       // 0..1 -> n offset *64
    const int gID = lane >> 2, tig = lane & 3;

    // triangular decode: blockIdx.x -> (bx >= by)
    int t = blockIdx.x;
    int a = (int)((sqrtf(8.0f * (float)t + 1.0f) - 1.0f) * 0.5f);
    while ((a + 1) * (a + 2) / 2 <= t) a++;
    while (a * (a + 1) / 2 > t) a--;
    const int bx = a;
    const int by = t - a * (a + 1) / 2;
    const int rowTile = by * TS;      // A rows (m)
    const int colTile = bx * TS;      // B rows (n)

    const uint32_t smbase = smem_u32(smf);

    float c[2][8][4];
#pragma unroll
    for (int i = 0; i < 2; i++)
#pragma unroll
        for (int j = 0; j < 8; j++)
#pragma unroll
            for (int q = 0; q < 4; q++) c[i][j][q] = 0.f;

    // stage loader: 4 tiles (AH, AL, BH, BL), each 128 rows x 32 floats
    auto issue_stage = [&](int stage, int k0) {
        const float* gsrc[4] = {g_hi, g_lo, g_hi, g_lo};
        const int    rbase[4] = {rowTile, rowTile, colTile, colTile};
#pragma unroll
        for (int tIdx = 0; tIdx < 4; tIdx++) {
            const float* src = gsrc[tIdx];
            uint32_t dstBase = smbase + (uint32_t)(stage * STAGE_F + tIdx * TILE_F) * 4u;
#pragma unroll
            for (int q = 0; q < 4; q++) {
                int seg = tid + q * 256;            // 0..1023
                int m = seg >> 3, s = seg & 7;      // row, 16B segment
                uint32_t d = dstBase + (uint32_t)(m * LDK + s * 4) * 4u;
                const float* g = src + (size_t)(rbase[tIdx] + m) * D_DIM + k0 + s * 4;
                CP_ASYNC_CG(d, g);
            }
        }
        CP_COMMIT();
    };

    issue_stage(0, 0);

    for (int it = 0; it < NSTAGE; it++) {
        if (it + 1 < NSTAGE) {
            issue_stage((it + 1) & 1, (it + 1) * KC);
            CP_WAIT(1);
        } else {
            CP_WAIT(0);
        }
        __syncthreads();

        const float* AH = smf + (it & 1) * STAGE_F;
        const float* AL = AH + TILE_F;
        const float* BH = AH + 2 * TILE_F;
        const float* BL = AH + 3 * TILE_F;

#pragma unroll
        for (int kk = 0; kk < 4; kk++) {           // four k8 steps per stage
            const int kb = kk * 8;
            uint32_t ah[2][4], al[2][4], bh[8][2], bl[8][2];
#pragma unroll
            for (int tm = 0; tm < 2; tm++) {
                int r0 = warpM * 32 + tm * 16 + gID;
                const float* p = AH + r0 * LDK + kb + tig;
                ah[tm][0] = __float_as_uint(p[0]);
                ah[tm][1] = __float_as_uint(p[8 * LDK]);
                ah[tm][2] = __float_as_uint(p[4]);
                ah[tm][3] = __float_as_uint(p[8 * LDK + 4]);
                const float* q = AL + r0 * LDK + kb + tig;
                al[tm][0] = __float_as_uint(q[0]);
                al[tm][1] = __float_as_uint(q[8 * LDK]);
                al[tm][2] = __float_as_uint(q[4]);
                al[tm][3] = __float_as_uint(q[8 * LDK + 4]);
            }
#pragma unroll
            for (int tn = 0; tn < 8; tn++) {
                int n0 = warpN * 64 + tn * 8 + gID;
                const float* p = BH + n0 * LDK + kb + tig;
                bh[tn][0] = __float_as_uint(p[0]);
                bh[tn][1] = __float_as_uint(p[4]);
                const float* q = BL + n0 * LDK + kb + tig;
                bl[tn][0] = __float_as_uint(q[0]);
                bl[tn][1] = __float_as_uint(q[4]);
            }
#pragma unroll
            for (int tm = 0; tm < 2; tm++)
#pragma unroll
                for (int tn = 0; tn < 8; tn++) {
                    MMA_TF32(c[tm][tn], ah[tm], bh[tn]);
                    MMA_TF32(c[tm][tn], ah[tm], bl[tn]);
                    MMA_TF32(c[tm][tn], al[tm], bh[tn]);
                }
        }
        __syncthreads();   // all warps done reading before buffer reuse
    }

    // Epilogue: d = sqrt(max(sq_r + sq_c - 2*dot, 0)); direct + mirror stores
#pragma unroll
    for (int tm = 0; tm < 2; tm++) {
        int r0 = rowTile + warpM * 32 + tm * 16 + gID;
        float sqr0 = g_sq[r0], sqr1 = g_sq[r0 + 8];
#pragma unroll
        for (int tn = 0; tn < 8; tn++) {
            int c0 = colTile + warpN * 64 + tn * 8 + 2 * tig;
            float sqc0 = g_sq[c0], sqc1 = g_sq[c0 + 1];
            float* C = c[tm][tn];
            float v00 = sqrtf(fmaxf(sqr0 + sqc0 - 2.f * C[0], 0.f));
            float v01 = sqrtf(fmaxf(sqr0 + sqc1 - 2.f * C[1], 0.f));
            float v10 = sqrtf(fmaxf(sqr1 + sqc0 - 2.f * C[2], 0.f));
            float v11 = sqrtf(fmaxf(sqr1 + sqc1 - 2.f * C[3], 0.f));
            *reinterpret_cast<float2*>(&g_dist[(size_t)r0 * T_DIM + c0]) =
                make_float2(v00, v01);
            *reinterpret_cast<float2*>(&g_dist[(size_t)(r0 + 8) * T_DIM + c0]) =
                make_float2(v10, v11);
            if (bx != by) {
                g_dist[(size_t)c0 * T_DIM + r0]           = v00;
                g_dist[(size_t)c0 * T_DIM + r0 + 8]       = v10;
                g_dist[(size_t)(c0 + 1) * T_DIM + r0]     = v01;
                g_dist[(size_t)(c0 + 1) * T_DIM + r0 + 8] = v11;
            }
        }
    }
}

// ---------------------------------------------------------------------------
// 4) Per-row top-5 smallest (dist, idx), jax.lax.top_k tie semantics
// ---------------------------------------------------------------------------
__device__ __forceinline__ bool kless(float d1, int i1, float d2, int i2) {
    return (d1 < d2) || (d1 == d2 && i1 < i2);
}
__device__ __forceinline__ void insert5(float d, int j, float (&d5)[5], int (&i5)[5]) {
    if (kless(d, j, d5[4], i5[4])) {
        d5[4] = d; i5[4] = j;
#pragma unroll
        for (int p = 4; p > 0; p--) {
            if (kless(d5[p], i5[p], d5[p - 1], i5[p - 1])) {
                float td = d5[p]; d5[p] = d5[p - 1]; d5[p - 1] = td;
                int   ti = i5[p]; i5[p] = i5[p - 1]; i5[p - 1] = ti;
            }
        }
    }
}

__global__ __launch_bounds__(256) void topk_kernel() {
    __shared__ float sd[256][5];
    __shared__ int   si[256][5];
    __shared__ float wd[8][5];
    __shared__ int   wi[8][5];

    int row = blockIdx.x;
    const float* drow = g_dist + (size_t)row * T_DIM;

    float d5[5]; int i5[5];
#pragma unroll
    for (int r = 0; r < 5; r++) { d5[r] = FLT_MAX; i5[r] = 0x7fffffff; }

    for (int j = threadIdx.x; j < T_DIM; j += 256) {
        float d = drow[j];
        insert5(d, j, d5, i5);
    }
#pragma unroll
    for (int r = 0; r < 5; r++) { sd[threadIdx.x][r] = d5[r]; si[threadIdx.x][r] = i5[r]; }
    __syncthreads();

    int lane = threadIdx.x & 31, wid = threadIdx.x >> 5;
    if (lane == 0) {
#pragma unroll
        for (int r = 0; r < 5; r++) { d5[r] = sd[wid * 32][r]; i5[r] = si[wid * 32][r]; }
        for (int t = 1; t < 32; t++) {
#pragma unroll
            for (int r = 0; r < 5; r++)
                insert5(sd[wid * 32 + t][r], si[wid * 32 + t][r], d5, i5);
        }
#pragma unroll
        for (int r = 0; r < 5; r++) { wd[wid][r] = d5[r]; wi[wid][r] = i5[r]; }
    }
    __syncthreads();

    if (threadIdx.x == 0) {
#pragma unroll
        for (int r = 0; r < 5; r++) { d5[r] = wd[0][r]; i5[r] = wi[0][r]; }
        for (int t = 1; t < 8; t++) {
#pragma unroll
            for (int r = 0; r < 5; r++)
                insert5(wd[t][r], wi[t][r], d5, i5);
        }
#pragma unroll
        for (int r = 0; r < 4; r++) g_nb[row * 4 + r] = i5[r + 1];
    }
}

// ---------------------------------------------------------------------------
// 5) Interpolate
// ---------------------------------------------------------------------------
__global__ __launch_bounds__(128) void synth_kernel(const float* __restrict__ X,
                                                    const float* __restrict__ gaps,
                                                    const int* __restrict__ choice,
                                                    float* __restrict__ out) {
    int s = blockIdx.x;
    int i = s >> 2;
    int c = choice[s];
    int sel = g_nb[i * 4 + c];
    float g = gaps[s];

    const float4* base = reinterpret_cast<const float4*>(X + (size_t)i * D_DIM);
    const float4* nb   = reinterpret_cast<const float4*>(X + (size_t)sel * D_DIM);
    float4* o = reinterpret_cast<float4*>(out + (size_t)s * D_DIM);

    int t = threadIdx.x;
    float4 b = base[t], v = nb[t];
    float4 r;
    r.x = fmaf(g, v.x - b.x, b.x);
    r.y = fmaf(g, v.y - b.y, b.y);
    r.z = fmaf(g, v.z - b.z, b.z);
    r.w = fmaf(g, v.w - b.w, b.w);
    o[t] = r;
}

// ---------------------------------------------------------------------------
extern "C" void kernel_launch(void* const* d_in, const int* in_sizes, int n_in,
                              void* d_out, int out_size) {
    const float* X      = (const float*)d_in[0];   // [8192, 512]
    const float* gaps   = (const float*)d_in[1];   // [8192, 4]
    const int*   choice = (const int*)d_in[2];     // [8192, 4]
    float* out = (float*)d_out;                    // [32768, 512]

    const int smem_bytes = 2 * STAGE_F * 4;        // 147456 B
    cudaFuncSetAttribute(dist_mma_kernel,
                         cudaFuncAttributeMaxDynamicSharedMemorySize, smem_bytes);

    sq_kernel<<<(T_DIM * 32 + 255) / 256, 256>>>(X);
    split_kernel<<<(T_DIM * D_DIM / 4) / 256, 256>>>(X);
    dist_mma_kernel<<<64 * 65 / 2, 256, smem_bytes>>>();
    topk_kernel<<<T_DIM, 256>>>();
    synth_kernel<<<T_DIM * N_SYN, 128>>>(X, gaps, choice, out);
}

// round 6
// speedup vs baseline: 2.8716x; 2.2663x over previous
#include <cuda_runtime.h>
#include <cuda_fp16.h>
#include <math.h>
#include <float.h>
#include <stdint.h>

#define T_DIM 8192
#define D_DIM 512
#define N_SYN 4
#define TS 128                    // CTA tile M=N
#define KC 64                     // k elems (halves) per smem stage
#define NSTAGE (D_DIM / KC)       // 8
#define LDKH 72                   // padded smem row stride in halves (144B, conflict-free)
#define TILE_H (TS * LDKH)        // halves per tile (9216)
#define STAGE_H (4 * TILE_H)      // AH AL BH BL (36864 halves = 73728 B)

// ---------------------------------------------------------------------------
// Device-global scratch
// ---------------------------------------------------------------------------
__device__ float g_sq[T_DIM];
__device__ float g_dist[(size_t)T_DIM * T_DIM];   // 256 MB
__device__ int   g_nb[T_DIM * 4];
__device__ __half g_hi[(size_t)T_DIM * D_DIM];    // 8 MB
__device__ __half g_lo[(size_t)T_DIM * D_DIM];    // 8 MB

// ---------------------------------------------------------------------------
// PTX helpers (baseline sm_80+ -> legal on compute_103)
// ---------------------------------------------------------------------------
__device__ __forceinline__ uint32_t smem_u32(const void* p) {
    uint32_t a;
    asm("{ .reg .u64 t; cvta.to.shared.u64 t, %1; cvt.u32.u64 %0, t; }" : "=r"(a) : "l"(p));
    return a;
}
#define CP_ASYNC_CG(dst_u32, src_ptr) \
    asm volatile("cp.async.cg.shared.global [%0], [%1], 16;" :: "r"(dst_u32), "l"(src_ptr))
#define CP_COMMIT() asm volatile("cp.async.commit_group;" ::: "memory")
#define CP_WAIT(n)  asm volatile("cp.async.wait_group %0;" :: "n"(n) : "memory")

#define MMA_F16(Cp, a, b) \
    asm volatile("mma.sync.aligned.m16n8k16.row.col.f32.f16.f16.f32 " \
        "{%0,%1,%2,%3}, {%4,%5,%6,%7}, {%8,%9}, {%0,%1,%2,%3};" \
        : "+f"((Cp)[0]), "+f"((Cp)[1]), "+f"((Cp)[2]), "+f"((Cp)[3]) \
        : "r"((a)[0]), "r"((a)[1]), "r"((a)[2]), "r"((a)[3]), \
          "r"((b)[0]), "r"((b)[1]))

// ---------------------------------------------------------------------------
// 1) Row squared norms (fp32): one warp per row
// ---------------------------------------------------------------------------
__global__ void sq_kernel(const float* __restrict__ X) {
    int warp = (blockIdx.x * blockDim.x + threadIdx.x) >> 5;
    int lane = threadIdx.x & 31;
    if (warp >= T_DIM) return;
    const float4* xr = reinterpret_cast<const float4*>(X + (size_t)warp * D_DIM);
    float s = 0.f;
#pragma unroll
    for (int c = 0; c < 4; c++) {
        float4 v = xr[lane + c * 32];
        s += v.x * v.x + v.y * v.y + v.z * v.z + v.w * v.w;
    }
#pragma unroll
    for (int o = 16; o > 0; o >>= 1) s += __shfl_down_sync(0xffffffffu, s, o);
    if (lane == 0) g_sq[warp] = s;
}

// ---------------------------------------------------------------------------
// 2) fp16 2-way split: x = hi + lo + r, |r| <= 2^-22 |x| (+ subnormal floor)
// ---------------------------------------------------------------------------
__global__ void split_kernel(const float* __restrict__ X) {
    int i = blockIdx.x * blockDim.x + threadIdx.x;   // over T*D/4
    float4 v = reinterpret_cast<const float4*>(X)[i];
    float xs[4] = {v.x, v.y, v.z, v.w};
    unsigned short h[4], l[4];
#pragma unroll
    for (int c = 0; c < 4; c++) {
        __half hh = __float2half_rn(xs[c]);
        float r = xs[c] - __half2float(hh);
        __half ll = __float2half_rn(r);
        h[c] = __half_as_ushort(hh);
        l[c] = __half_as_ushort(ll);
    }
    reinterpret_cast<ushort4*>(g_hi)[i] = make_ushort4(h[0], h[1], h[2], h[3]);
    reinterpret_cast<ushort4*>(g_lo)[i] = make_ushort4(l[0], l[1], l[2], l[3]);
}

// ---------------------------------------------------------------------------
// 3) Triangular dist GEMM via mma.sync fp16 m16n8k16 (dot = hh + hl + lh)
//    256 threads = 8 warps (4x2), warp tile 32x64, CTA tile 128x128.
// ---------------------------------------------------------------------------
__global__ __launch_bounds__(256, 1) void dist_mma_kernel() {
    extern __shared__ __align__(16) __half smh[];
    const int tid = threadIdx.x;
    const int lane = tid & 31, wid = tid >> 5;
    const int warpM = wid & 3;        // m offset *32
    const int warpN = wid >> 2;       // n offset *64
    const int gID = lane >> 2, tig = lane & 3;

    // triangular decode: blockIdx.x -> (bx >= by)
    int t = blockIdx.x;
    int a = (int)((sqrtf(8.0f * (float)t + 1.0f) - 1.0f) * 0.5f);
    while ((a + 1) * (a + 2) / 2 <= t) a++;
    while (a * (a + 1) / 2 > t) a--;
    const int bx = a;
    const int by = t - a * (a + 1) / 2;
    const int rowTile = by * TS;
    const int colTile = bx * TS;

    const uint32_t smbase = smem_u32(smh);

    float c[2][8][4];
#pragma unroll
    for (int i = 0; i < 2; i++)
#pragma unroll
        for (int j = 0; j < 8; j++)
#pragma unroll
            for (int q = 0; q < 4; q++) c[i][j][q] = 0.f;

    // stage loader: 4 tiles (AH, AL, BH, BL), each 128 rows x 64 halves (128B rows)
    auto issue_stage = [&](int stage, int k0) {
        const __half* gsrc[4] = {g_hi, g_lo, g_hi, g_lo};
        const int    rbase[4] = {rowTile, rowTile, colTile, colTile};
#pragma unroll
        for (int tIdx = 0; tIdx < 4; tIdx++) {
            const __half* src = gsrc[tIdx];
            uint32_t dstBase = smbase + (uint32_t)(stage * STAGE_H + tIdx * TILE_H) * 2u;
#pragma unroll
            for (int q = 0; q < 4; q++) {
                int seg = tid + q * 256;            // 0..1023
                int m = seg >> 3, s = seg & 7;      // row, 16B segment (8 halves)
                uint32_t d = dstBase + (uint32_t)(m * LDKH + s * 8) * 2u;
                const __half* g = src + (size_t)(rbase[tIdx] + m) * D_DIM + k0 + s * 8;
                CP_ASYNC_CG(d, g);
            }
        }
        CP_COMMIT();
    };

    issue_stage(0, 0);

    for (int it = 0; it < NSTAGE; it++) {
        if (it + 1 < NSTAGE) {
            issue_stage((it + 1) & 1, (it + 1) * KC);
            CP_WAIT(1);
        } else {
            CP_WAIT(0);
        }
        __syncthreads();

        const __half* AH = smh + (it & 1) * STAGE_H;
        const __half* AL = AH + TILE_H;
        const __half* BH = AH + 2 * TILE_H;
        const __half* BL = AH + 3 * TILE_H;

#pragma unroll
        for (int kk = 0; kk < 4; kk++) {           // four k16 steps per stage
            const int kb = kk * 16;
            uint32_t ah[2][4], al[2][4], bh[8][2], bl[8][2];
#pragma unroll
            for (int tm = 0; tm < 2; tm++) {
                int r0 = warpM * 32 + tm * 16 + gID;
                const __half* p = AH + r0 * LDKH + kb + 2 * tig;
                ah[tm][0] = *reinterpret_cast<const uint32_t*>(p);
                ah[tm][1] = *reinterpret_cast<const uint32_t*>(p + 8 * LDKH);
                ah[tm][2] = *reinterpret_cast<const uint32_t*>(p + 8);
                ah[tm][3] = *reinterpret_cast<const uint32_t*>(p + 8 * LDKH + 8);
                const __half* q = AL + r0 * LDKH + kb + 2 * tig;
                al[tm][0] = *reinterpret_cast<const uint32_t*>(q);
                al[tm][1] = *reinterpret_cast<const uint32_t*>(q + 8 * LDKH);
                al[tm][2] = *reinterpret_cast<const uint32_t*>(q + 8);
                al[tm][3] = *reinterpret_cast<const uint32_t*>(q + 8 * LDKH + 8);
            }
#pragma unroll
            for (int tn = 0; tn < 8; tn++) {
                int n0 = warpN * 64 + tn * 8 + gID;
                const __half* p = BH + n0 * LDKH + kb + 2 * tig;
                bh[tn][0] = *reinterpret_cast<const uint32_t*>(p);
                bh[tn][1] = *reinterpret_cast<const uint32_t*>(p + 8);
                const __half* q = BL + n0 * LDKH + kb + 2 * tig;
                bl[tn][0] = *reinterpret_cast<const uint32_t*>(q);
                bl[tn][1] = *reinterpret_cast<const uint32_t*>(q + 8);
            }
#pragma unroll
            for (int tm = 0; tm < 2; tm++)
#pragma unroll
                for (int tn = 0; tn < 8; tn++) {
                    MMA_F16(c[tm][tn], ah[tm], bh[tn]);
                    MMA_F16(c[tm][tn], ah[tm], bl[tn]);
                    MMA_F16(c[tm][tn], al[tm], bh[tn]);
                }
        }
        __syncthreads();
    }

    // Epilogue: d = sqrt(max(sq_r + sq_c - 2*dot, 0)); direct + mirror stores
#pragma unroll
    for (int tm = 0; tm < 2; tm++) {
        int r0 = rowTile + warpM * 32 + tm * 16 + gID;
        float sqr0 = g_sq[r0], sqr1 = g_sq[r0 + 8];
#pragma unroll
        for (int tn = 0; tn < 8; tn++) {
            int c0 = colTile + warpN * 64 + tn * 8 + 2 * tig;
            float sqc0 = g_sq[c0], sqc1 = g_sq[c0 + 1];
            float* C = c[tm][tn];
            float v00 = sqrtf(fmaxf(sqr0 + sqc0 - 2.f * C[0], 0.f));
            float v01 = sqrtf(fmaxf(sqr0 + sqc1 - 2.f * C[1], 0.f));
            float v10 = sqrtf(fmaxf(sqr1 + sqc0 - 2.f * C[2], 0.f));
            float v11 = sqrtf(fmaxf(sqr1 + sqc1 - 2.f * C[3], 0.f));
            *reinterpret_cast<float2*>(&g_dist[(size_t)r0 * T_DIM + c0]) =
                make_float2(v00, v01);
            *reinterpret_cast<float2*>(&g_dist[(size_t)(r0 + 8) * T_DIM + c0]) =
                make_float2(v10, v11);
            if (bx != by) {
                g_dist[(size_t)c0 * T_DIM + r0]           = v00;
                g_dist[(size_t)c0 * T_DIM + r0 + 8]       = v10;
                g_dist[(size_t)(c0 + 1) * T_DIM + r0]     = v01;
                g_dist[(size_t)(c0 + 1) * T_DIM + r0 + 8] = v11;
            }
        }
    }
}

// ---------------------------------------------------------------------------
// 4) Per-row top-5 smallest (dist, idx), jax.lax.top_k tie semantics.
//    Fast path: float-only threshold compare; rare path: exact lexicographic.
// ---------------------------------------------------------------------------
__device__ __forceinline__ bool kless(float d1, int i1, float d2, int i2) {
    return (d1 < d2) || (d1 == d2 && i1 < i2);
}
__device__ __forceinline__ void insert5(float d, int j, float (&d5)[5], int (&i5)[5]) {
    if (kless(d, j, d5[4], i5[4])) {
        d5[4] = d; i5[4] = j;
#pragma unroll
        for (int p = 4; p > 0; p--) {
            if (kless(d5[p], i5[p], d5[p - 1], i5[p - 1])) {
                float td = d5[p]; d5[p] = d5[p - 1]; d5[p - 1] = td;
                int   ti = i5[p]; i5[p] = i5[p - 1]; i5[p - 1] = ti;
            }
        }
    }
}

__global__ __launch_bounds__(256) void topk_kernel() {
    __shared__ float sd[256][5];
    __shared__ int   si[256][5];
    __shared__ float wd[8][5];
    __shared__ int   wi[8][5];

    int row = blockIdx.x;
    const float4* drow4 = reinterpret_cast<const float4*>(g_dist + (size_t)row * T_DIM);

    float d5[5]; int i5[5];
#pragma unroll
    for (int r = 0; r < 5; r++) { d5[r] = FLT_MAX; i5[r] = 0x7fffffff; }

    for (int j4 = threadIdx.x; j4 < T_DIM / 4; j4 += 256) {
        float4 v = drow4[j4];
        int jb = j4 << 2;
        if (v.x <= d5[4]) insert5(v.x, jb,     d5, i5);
        if (v.y <= d5[4]) insert5(v.y, jb + 1, d5, i5);
        if (v.z <= d5[4]) insert5(v.z, jb + 2, d5, i5);
        if (v.w <= d5[4]) insert5(v.w, jb + 3, d5, i5);
    }
#pragma unroll
    for (int r = 0; r < 5; r++) { sd[threadIdx.x][r] = d5[r]; si[threadIdx.x][r] = i5[r]; }
    __syncthreads();

    int lane = threadIdx.x & 31, wid = threadIdx.x >> 5;
    if (lane == 0) {
#pragma unroll
        for (int r = 0; r < 5; r++) { d5[r] = sd[wid * 32][r]; i5[r] = si[wid * 32][r]; }
        for (int t = 1; t < 32; t++) {
#pragma unroll
            for (int r = 0; r < 5; r++)
                insert5(sd[wid * 32 + t][r], si[wid * 32 + t][r], d5, i5);
        }
#pragma unroll
        for (int r = 0; r < 5; r++) { wd[wid][r] = d5[r]; wi[wid][r] = i5[r]; }
    }
    __syncthreads();

    if (threadIdx.x == 0) {
#pragma unroll
        for (int r = 0; r < 5; r++) { d5[r] = wd[0][r]; i5[r] = wi[0][r]; }
        for (int t = 1; t < 8; t++) {
#pragma unroll
            for (int r = 0; r < 5; r++)
                insert5(wd[t][r], wi[t][r], d5, i5);
        }
#pragma unroll
        for (int r = 0; r < 4; r++) g_nb[row * 4 + r] = i5[r + 1];
    }
}

// ---------------------------------------------------------------------------
// 5) Interpolate
// ---------------------------------------------------------------------------
__global__ __launch_bounds__(128) void synth_kernel(const float* __restrict__ X,
                                                    const float* __restrict__ gaps,
                                                    const int* __restrict__ choice,
                                                    float* __restrict__ out) {
    int s = blockIdx.x;
    int i = s >> 2;
    int c = choice[s];
    int sel = g_nb[i * 4 + c];
    float g = gaps[s];

    const float4* base = reinterpret_cast<const float4*>(X + (size_t)i * D_DIM);
    const float4* nb   = reinterpret_cast<const float4*>(X + (size_t)sel * D_DIM);
    float4* o = reinterpret_cast<float4*>(out + (size_t)s * D_DIM);

    int t = threadIdx.x;
    float4 b = base[t], v = nb[t];
    float4 r;
    r.x = fmaf(g, v.x - b.x, b.x);
    r.y = fmaf(g, v.y - b.y, b.y);
    r.z = fmaf(g, v.z - b.z, b.z);
    r.w = fmaf(g, v.w - b.w, b.w);
    o[t] = r;
}

// ---------------------------------------------------------------------------
extern "C" void kernel_launch(void* const* d_in, const int* in_sizes, int n_in,
                              void* d_out, int out_size) {
    const float* X      = (const float*)d_in[0];   // [8192, 512]
    const float* gaps   = (const float*)d_in[1];   // [8192, 4]
    const int*   choice = (const int*)d_in[2];     // [8192, 4]
    float* out = (float*)d_out;                    // [32768, 512]

    const int smem_bytes = 2 * STAGE_H * 2;        // 147456 B
    cudaFuncSetAttribute(dist_mma_kernel,
                         cudaFuncAttributeMaxDynamicSharedMemorySize, smem_bytes);

    sq_kernel<<<(T_DIM * 32 + 255) / 256, 256>>>(X);
    split_kernel<<<(T_DIM * D_DIM / 4) / 256, 256>>>(X);
    dist_mma_kernel<<<64 * 65 / 2, 256, smem_bytes>>>();
    topk_kernel<<<T_DIM, 256>>>();
    synth_kernel<<<T_DIM * N_SYN, 128>>>(X, gaps, choice, out);
}